// round 11
// baseline (speedup 1.0000x reference)
#include <cuda_runtime.h>
#include <cuda_bf16.h>
#include <cstdint>

#define B_   4
#define T_   2048
#define C_   1024
#define H_   16
#define D_   64
#define BT_  (B_*T_)
#define BH_  (B_*H_)
#define K3_  3072     // logical 3-segment K for projections
#define K2_  2048     // A stored as [hi|lo] only (seg2 == seg0)

// ------------------------- scratch (device globals) -------------------------
__device__ __align__(16) float g_O[BT_*C_];                  // [B][T][C]
__device__ __align__(16) unsigned short g_A [BT_*K2_];       // x-split / O-split [hi|lo]
__device__ __align__(16) unsigned short g_Bq[3*C_*K3_];      // Wqkv^T split [hi|hi|lo]
__device__ __align__(16) unsigned short g_Bo[C_*K3_];        // Wout^T split [hi|hi|lo]
__device__ __align__(16) unsigned short g_Qs[BH_*T_*128];    // [bh][t][hi64|lo64], Q pre-scaled
__device__ __align__(16) unsigned short g_Ks[BH_*T_*128];    // [bh][t][hi64|lo64]
__device__ __align__(16) unsigned short g_Vt[BH_*128*T_];    // [bh][hi d0..63, lo d0..63][t]

// ------------------------------ small helpers -------------------------------
__device__ __forceinline__ uint32_t s2u(const void* p) {
    uint32_t a;
    asm("{ .reg .u64 t; cvta.to.shared.u64 t, %1; cvt.u32.u64 %0, t; }" : "=r"(a) : "l"(p));
    return a;
}
__device__ __forceinline__ void cp16(uint32_t d, const void* s) {
    asm volatile("cp.async.cg.shared.global [%0], [%1], 16;" :: "r"(d), "l"(s));
}
__device__ __forceinline__ void ldsm4(uint32_t& r0, uint32_t& r1, uint32_t& r2, uint32_t& r3,
                                      uint32_t a) {
    asm volatile("ldmatrix.sync.aligned.m8n8.x4.shared.b16 {%0,%1,%2,%3}, [%4];"
                 : "=r"(r0), "=r"(r1), "=r"(r2), "=r"(r3) : "r"(a));
}
__device__ __forceinline__ void mma16816(float* c, const uint32_t* a, const uint32_t* b) {
    asm volatile("mma.sync.aligned.m16n8k16.row.col.f32.bf16.bf16.f32 "
                 "{%0,%1,%2,%3}, {%4,%5,%6,%7}, {%8,%9}, {%0,%1,%2,%3};"
                 : "+f"(c[0]), "+f"(c[1]), "+f"(c[2]), "+f"(c[3])
                 : "r"(a[0]), "r"(a[1]), "r"(a[2]), "r"(a[3]), "r"(b[0]), "r"(b[1]));
}
// pack two floats into bf16x2: low half = first arg
__device__ __forceinline__ uint32_t pk_bf2(float lo, float hi) {
    uint32_t d;
    asm("cvt.rn.bf16x2.f32 %0, %1, %2;" : "=r"(d) : "f"(hi), "f"(lo));
    return d;
}
__device__ __forceinline__ float bf2_lo(uint32_t u) { return __uint_as_float(u << 16); }
__device__ __forceinline__ float bf2_hi(uint32_t u) { return __uint_as_float(u & 0xffff0000u); }

// ------------------------------ prep kernels --------------------------------
// split fp32 [rows][1024] -> bf16 [rows][2048] = [hi | lo]
__global__ __launch_bounds__(256) void prep_split_kernel(
    const float* __restrict__ src, unsigned short* __restrict__ dst)
{
    int idx = blockIdx.x * 256 + threadIdx.x;
    int row = idx >> 8;
    int c4  = idx & 255;
    float4 v = *(const float4*)(src + (size_t)row * 1024 + c4 * 4);
    float f[4] = {v.x, v.y, v.z, v.w};
    unsigned short h[4], l[4];
    #pragma unroll
    for (int i = 0; i < 4; i++) {
        __nv_bfloat16 hb = __float2bfloat16(f[i]);
        __nv_bfloat16 lb = __float2bfloat16(f[i] - __bfloat162float(hb));
        h[i] = __bfloat16_as_ushort(hb);
        l[i] = __bfloat16_as_ushort(lb);
    }
    uint64_t hp = (uint64_t)h[0] | ((uint64_t)h[1] << 16) | ((uint64_t)h[2] << 32) | ((uint64_t)h[3] << 48);
    uint64_t lp = (uint64_t)l[0] | ((uint64_t)l[1] << 16) | ((uint64_t)l[2] << 32) | ((uint64_t)l[3] << 48);
    unsigned short* rp = dst + (size_t)row * K2_ + c4 * 4;
    *(uint64_t*)(rp)        = hp;
    *(uint64_t*)(rp + 1024) = lp;
}

// transpose + split: W[1024][N] fp32 -> dst[N][3072] = [hi | hi | lo]
template<int N>
__global__ __launch_bounds__(256) void prep_wsplit_kernel(
    const float* __restrict__ W, unsigned short* __restrict__ dst)
{
    __shared__ float tile[32][33];
    int n0 = blockIdx.x * 32, k0 = blockIdx.y * 32;
    int tx = threadIdx.x, ty = threadIdx.y;
    #pragma unroll
    for (int i = 0; i < 32; i += 8)
        tile[ty + i][tx] = W[(size_t)(k0 + ty + i) * N + n0 + tx];
    __syncthreads();
    #pragma unroll
    for (int i = 0; i < 32; i += 8) {
        int n = n0 + ty + i;
        int k = k0 + tx;
        float v = tile[tx][ty + i];
        __nv_bfloat16 hb = __float2bfloat16(v);
        __nv_bfloat16 lb = __float2bfloat16(v - __bfloat162float(hb));
        unsigned short hu = __bfloat16_as_ushort(hb);
        unsigned short lu = __bfloat16_as_ushort(lb);
        unsigned short* rp = dst + (size_t)n * K3_ + k;
        rp[0]    = hu;
        rp[1024] = hu;
        rp[2048] = lu;
    }
}

// ---------------------- mma.sync bf16 GEMM (tensor core) ---------------------
// D[128,128] = A[128, K2 as 3-seg] . B[128, K3]^T.
// 128 threads = 4 warps, warp tile 64x64, K-chunk 64, 2-stage, 1 sync/chunk.
#define KCH   64
#define TSTR2 144                        // bytes per 64-k row (128 B + 16 pad)
#define TILE2 (128 * TSTR2)              // 18432
#define STG2  (2 * TILE2)                // A+B per stage = 36864
#define GSMEM (2 * STG2)                 // 73728 (2-stage)
#define NCHU  (K3_ / KCH)                // 48
#define ROWA  (K2_ * 2)                  // 4096 B
#define ROWB  (K3_ * 2)                  // 6144 B

template<int MODE>
__global__ __launch_bounds__(128, 2) void gemm_mma_kernel(
    const unsigned short* __restrict__ A, const unsigned short* __restrict__ Bm,
    const float* __restrict__ bias, float* __restrict__ Cout)
{
    extern __shared__ __align__(128) char smem[];
    const uint32_t sb = s2u(smem);

    const int tid = threadIdx.x, wid = tid >> 5, lid = tid & 31;
    const int bm = blockIdx.y * 128, bn = blockIdx.x * 128;
    const int wm = (wid & 1) * 64, wn = (wid >> 1) * 64;

    const int g = lid >> 3, r = lid & 7;
    const uint32_t aoff = (uint32_t)(((g & 1) * 8 + r) * TSTR2 + (g >> 1) * 16);
    const uint32_t boff = (uint32_t)(((g >> 1) * 8 + r) * TSTR2 + (g & 1) * 16);

    const char* gA0 = (const char*)A  + (size_t)bm * ROWA;
    const char* gB0 = (const char*)Bm + (size_t)bn * ROWB;

    #define LOADCHUNK(kc, buf) do {                                            \
        int ac_ = (kc) < 32 ? (kc) : (kc) - 32;   /* A seg2 == seg0 */         \
        uint32_t b0 = sb + (buf) * STG2;                                       \
        _Pragma("unroll")                                                      \
        for (int i_ = 0; i_ < 8; i_++) {                                       \
            int idx_ = tid + i_ * 128;                                         \
            int row_ = idx_ >> 3, c_ = idx_ & 7;                               \
            cp16(b0 + (uint32_t)(row_ * TSTR2 + c_ * 16),                      \
                 gA0 + (size_t)row_ * ROWA + ac_ * 128 + c_ * 16);             \
            cp16(b0 + TILE2 + (uint32_t)(row_ * TSTR2 + c_ * 16),              \
                 gB0 + (size_t)row_ * ROWB + (size_t)(kc) * 128 + c_ * 16);    \
        }                                                                      \
        asm volatile("cp.async.commit_group;" ::: "memory");                   \
    } while (0)

    float acc[4][8][4];
    #pragma unroll
    for (int mt = 0; mt < 4; mt++)
        #pragma unroll
        for (int nt = 0; nt < 8; nt++)
            #pragma unroll
            for (int i = 0; i < 4; i++) acc[mt][nt][i] = 0.f;

    LOADCHUNK(0, 0);

    for (int c = 0; c < NCHU; c++) {
        asm volatile("cp.async.wait_group 0;" ::: "memory");
        __syncthreads();
        if (c + 1 < NCHU) LOADCHUNK(c + 1, (c + 1) & 1);

        const uint32_t sAb = sb + (c & 1) * STG2;
        const uint32_t sBb = sAb + TILE2;
        #pragma unroll
        for (int ks = 0; ks < 4; ks++) {
            uint32_t a[4][4];
            #pragma unroll
            for (int mt = 0; mt < 4; mt++)
                ldsm4(a[mt][0], a[mt][1], a[mt][2], a[mt][3],
                      sAb + (uint32_t)((wm + mt * 16) * TSTR2 + ks * 32) + aoff);
            uint32_t b[8][2];
            #pragma unroll
            for (int nh = 0; nh < 4; nh++) {
                uint32_t r0, r1, r2, r3;
                ldsm4(r0, r1, r2, r3,
                      sBb + (uint32_t)((wn + nh * 16) * TSTR2 + ks * 32) + boff);
                b[nh*2+0][0] = r0; b[nh*2+0][1] = r1;
                b[nh*2+1][0] = r2; b[nh*2+1][1] = r3;
            }
            #pragma unroll
            for (int mt = 0; mt < 4; mt++)
                #pragma unroll
                for (int nt = 0; nt < 8; nt++)
                    mma16816(acc[mt][nt], a[mt], b[nt]);
        }
    }

    // ------------------------------- epilogue --------------------------------
    const int mrow = bm + wm + (lid >> 2);
    const int ncol = bn + wn + (lid & 3) * 2;
    #pragma unroll
    for (int mt = 0; mt < 4; mt++) {
        #pragma unroll
        for (int half = 0; half < 2; half++) {
            int m = mrow + mt * 16 + half * 8;
            #pragma unroll
            for (int nt = 0; nt < 8; nt++) {
                int col = ncol + nt * 8;
                float vx = acc[mt][nt][half * 2 + 0] + bias[col];
                float vy = acc[mt][nt][half * 2 + 1] + bias[col + 1];
                if (MODE == 0) {
                    const int which = bn >> 10;          // uniform per block
                    int ccv = col & 1023;
                    int hh = ccv >> 6, d = ccv & 63;
                    int bb = m >> 11, t = m & 2047;
                    int bh = bb * H_ + hh;
                    if (which == 0) {                    // Q: pre-scale by 1/sqrt(64)
                        vx *= 0.125f; vy *= 0.125f;
                        uint32_t hi2 = pk_bf2(vx, vy);
                        uint32_t lo2 = pk_bf2(vx - bf2_lo(hi2), vy - bf2_hi(hi2));
                        size_t idx = ((size_t)bh * T_ + t) * 128 + d;
                        *(uint32_t*)&g_Qs[idx]      = hi2;
                        *(uint32_t*)&g_Qs[idx + 64] = lo2;
                    } else if (which == 1) {             // K
                        uint32_t hi2 = pk_bf2(vx, vy);
                        uint32_t lo2 = pk_bf2(vx - bf2_lo(hi2), vy - bf2_hi(hi2));
                        size_t idx = ((size_t)bh * T_ + t) * 128 + d;
                        *(uint32_t*)&g_Ks[idx]      = hi2;
                        *(uint32_t*)&g_Ks[idx + 64] = lo2;
                    } else {                             // V -> transposed split
                        uint32_t hi2 = pk_bf2(vx, vy);
                        uint32_t lo2 = pk_bf2(vx - bf2_lo(hi2), vy - bf2_hi(hi2));
                        size_t rb = (size_t)bh * 128;
                        g_Vt[(rb + d         ) * T_ + t] = (unsigned short)(hi2 & 0xffff);
                        g_Vt[(rb + d + 1     ) * T_ + t] = (unsigned short)(hi2 >> 16);
                        g_Vt[(rb + 64 + d    ) * T_ + t] = (unsigned short)(lo2 & 0xffff);
                        g_Vt[(rb + 64 + d + 1) * T_ + t] = (unsigned short)(lo2 >> 16);
                    }
                } else {
                    float2 v; v.x = vx; v.y = vy;
                    *(float2*)&Cout[(size_t)m * 1024 + col] = v;
                }
            }
        }
    }
    #undef LOADCHUNK
}

// ------------------- flash attention (tensor core, bf16 split) ---------------
#define QSTR    272                      // smem row stride bytes (136 bf16)
#define FK_TILE (64 * QSTR)              // 17408
#define FLASH_SMEM (128 * QSTR + 4 * FK_TILE)   // 104448

__global__ __launch_bounds__(128) void flash_mma_kernel()
{
    extern __shared__ char fsm[];
    const uint32_t sQ  = s2u(fsm);
    const uint32_t sK0 = sQ + 128 * QSTR;
    const uint32_t sV0 = sK0 + 2 * FK_TILE;

    const int tid = threadIdx.x, wid = tid >> 5, lid = tid & 31;
    const int qb = blockIdx.x * 128, h = blockIdx.y, b = blockIdx.z;
    const int bh = b * H_ + h;
    const int qwb = qb + wid * 32;

    const char* Qg = (const char*)(g_Qs + ((size_t)bh * T_ + qb) * 128);
    const char* Kg = (const char*)(g_Ks + ((size_t)bh * T_) * 128);
    const char* Vg = (const char*)(g_Vt + (size_t)bh * 128 * T_);

    // Q tile (128 rows x 256B) -> smem
    #pragma unroll
    for (int i = 0; i < 16; i++) {
        int idx = tid + i * 128, row = idx >> 4, c16 = idx & 15;
        cp16(sQ + row * QSTR + c16 * 16, Qg + row * 256 + c16 * 16);
    }
    asm volatile("cp.async.commit_group;" ::: "memory");

    #define LOADKV(kb_, buf_) do {                                               \
        uint32_t sk = sK0 + (buf_) * FK_TILE, sv = sV0 + (buf_) * FK_TILE;       \
        _Pragma("unroll")                                                        \
        for (int i_ = 0; i_ < 8; i_++) {                                         \
            int idx = tid + i_ * 128, row = idx >> 4, c16 = idx & 15;            \
            cp16(sk + row * QSTR + c16 * 16,                                     \
                 Kg + (size_t)((kb_) + row) * 256 + c16 * 16);                   \
            int seg = c16 >> 3, kc = c16 & 7;                                    \
            cp16(sv + row * QSTR + c16 * 16,                                     \
                 Vg + (size_t)(seg * 64 + row) * 4096 + (size_t)(kb_) * 2 + kc * 16); \
        }                                                                        \
        asm volatile("cp.async.commit_group;" ::: "memory");                     \
    } while (0)

    LOADKV(0, 0);

    const int g = lid >> 3, r = lid & 7;
    const uint32_t aoff  = (uint32_t)(((g & 1) * 8 + r) * QSTR + (g >> 1) * 16);
    const uint32_t boff  = (uint32_t)(((g >> 1) * 8 + r) * QSTR + (g & 1) * 16);
    const uint32_t qwoff = (uint32_t)(wid * 32) * QSTR;

    float O[2][8][4];
    #pragma unroll
    for (int mt = 0; mt < 2; mt++)
        #pragma unroll
        for (int nt = 0; nt < 8; nt++)
            #pragma unroll
            for (int i = 0; i < 4; i++) O[mt][nt][i] = 0.f;
    float mrow[2][2] = {{-1e30f, -1e30f}, {-1e30f, -1e30f}};
    float lrow[2][2] = {{0.f, 0.f}, {0.f, 0.f}};

    const int ntiles = (qb + 128) >> 6;

    for (int t = 0; t < ntiles; t++) {
        const int kb = t << 6;
        asm volatile("cp.async.wait_group 0;" ::: "memory");
        __syncthreads();
        if (t + 1 < ntiles) LOADKV((t + 1) << 6, (t + 1) & 1);

        if (kb <= qwb + 31) {
            const uint32_t sK = sK0 + (t & 1) * FK_TILE;
            const uint32_t sV = sV0 + (t & 1) * FK_TILE;

            // ---- S = Q . K^T (3-term split) ----
            float S[2][8][4];
            #pragma unroll
            for (int mt = 0; mt < 2; mt++)
                #pragma unroll
                for (int nt = 0; nt < 8; nt++)
                    #pragma unroll
                    for (int i = 0; i < 4; i++) S[mt][nt][i] = 0.f;

            #pragma unroll
            for (int pass = 0; pass < 3; pass++) {
                const uint32_t aseg = (pass == 1) ? 128u : 0u;   // Q lo segment
                const uint32_t bseg = (pass == 2) ? 128u : 0u;   // K lo segment
                #pragma unroll
                for (int kt = 0; kt < 4; kt++) {
                    uint32_t a0[4], a1[4];
                    ldsm4(a0[0], a0[1], a0[2], a0[3],
                          sQ + qwoff + aseg + kt * 32 + aoff);
                    ldsm4(a1[0], a1[1], a1[2], a1[3],
                          sQ + qwoff + 16 * QSTR + aseg + kt * 32 + aoff);
                    #pragma unroll
                    for (int np = 0; np < 4; np++) {
                        uint32_t b0, b1, b2, b3;
                        ldsm4(b0, b1, b2, b3,
                              sK + (uint32_t)(np * 16) * QSTR + bseg + kt * 32 + boff);
                        uint32_t bb0[2] = {b0, b1}, bb1[2] = {b2, b3};
                        mma16816(S[0][np * 2 + 0], a0, bb0);
                        mma16816(S[0][np * 2 + 1], a0, bb1);
                        mma16816(S[1][np * 2 + 0], a1, bb0);
                        mma16816(S[1][np * 2 + 1], a1, bb1);
                    }
                }
            }

            // ---- causal mask ----
            if (kb + 63 > qwb) {
                #pragma unroll
                for (int mt = 0; mt < 2; mt++) {
                    int q0 = qwb + mt * 16 + (lid >> 2);
                    #pragma unroll
                    for (int nt = 0; nt < 8; nt++) {
                        int key = kb + nt * 8 + (lid & 3) * 2;
                        if (key     > q0)     S[mt][nt][0] = -1e30f;
                        if (key + 1 > q0)     S[mt][nt][1] = -1e30f;
                        if (key     > q0 + 8) S[mt][nt][2] = -1e30f;
                        if (key + 1 > q0 + 8) S[mt][nt][3] = -1e30f;
                    }
                }
            }

            // ---- online softmax + P split ----
            uint32_t phi[2][4][4], plo[2][4][4];
            #pragma unroll
            for (int mt = 0; mt < 2; mt++) {
                float mn0 = -1e30f, mn1 = -1e30f;
                #pragma unroll
                for (int nt = 0; nt < 8; nt++) {
                    mn0 = fmaxf(mn0, fmaxf(S[mt][nt][0], S[mt][nt][1]));
                    mn1 = fmaxf(mn1, fmaxf(S[mt][nt][2], S[mt][nt][3]));
                }
                mn0 = fmaxf(mn0, __shfl_xor_sync(0xffffffffu, mn0, 1));
                mn0 = fmaxf(mn0, __shfl_xor_sync(0xffffffffu, mn0, 2));
                mn1 = fmaxf(mn1, __shfl_xor_sync(0xffffffffu, mn1, 1));
                mn1 = fmaxf(mn1, __shfl_xor_sync(0xffffffffu, mn1, 2));
                float mx0 = fmaxf(mrow[mt][0], mn0), mx1 = fmaxf(mrow[mt][1], mn1);
                float al0 = __expf(mrow[mt][0] - mx0), al1 = __expf(mrow[mt][1] - mx1);
                mrow[mt][0] = mx0; mrow[mt][1] = mx1;
                float s0 = 0.f, s1 = 0.f;
                #pragma unroll
                for (int nt = 0; nt < 8; nt++) {
                    float p0 = __expf(S[mt][nt][0] - mx0);
                    float p1 = __expf(S[mt][nt][1] - mx0);
                    float p2 = __expf(S[mt][nt][2] - mx1);
                    float p3 = __expf(S[mt][nt][3] - mx1);
                    s0 += p0 + p1; s1 += p2 + p3;
                    S[mt][nt][0] = p0; S[mt][nt][1] = p1;
                    S[mt][nt][2] = p2; S[mt][nt][3] = p3;
                }
                s0 += __shfl_xor_sync(0xffffffffu, s0, 1);
                s0 += __shfl_xor_sync(0xffffffffu, s0, 2);
                s1 += __shfl_xor_sync(0xffffffffu, s1, 1);
                s1 += __shfl_xor_sync(0xffffffffu, s1, 2);
                lrow[mt][0] = lrow[mt][0] * al0 + s0;
                lrow[mt][1] = lrow[mt][1] * al1 + s1;
                #pragma unroll
                for (int nt = 0; nt < 8; nt++) {
                    O[mt][nt][0] *= al0; O[mt][nt][1] *= al0;
                    O[mt][nt][2] *= al1; O[mt][nt][3] *= al1;
                }
                // pack P fragments: C-frag(ntiles 2kt,2kt+1) -> A-frag(k16 tile kt)
                #pragma unroll
                for (int kt = 0; kt < 4; kt++) {
                    uint32_t h0 = pk_bf2(S[mt][2*kt  ][0], S[mt][2*kt  ][1]);
                    uint32_t h1 = pk_bf2(S[mt][2*kt  ][2], S[mt][2*kt  ][3]);
                    uint32_t h2 = pk_bf2(S[mt][2*kt+1][0], S[mt][2*kt+1][1]);
                    uint32_t h3 = pk_bf2(S[mt][2*kt+1][2], S[mt][2*kt+1][3]);
                    phi[mt][kt][0] = h0; phi[mt][kt][1] = h1;
                    phi[mt][kt][2] = h2; phi[mt][kt][3] = h3;
                    plo[mt][kt][0] = pk_bf2(S[mt][2*kt  ][0] - bf2_lo(h0),
                                            S[mt][2*kt  ][1] - bf2_hi(h0));
                    plo[mt][kt][1] = pk_bf2(S[mt][2*kt  ][2] - bf2_lo(h1),
                                            S[mt][2*kt  ][3] - bf2_hi(h1));
                    plo[mt][kt][2] = pk_bf2(S[mt][2*kt+1][0] - bf2_lo(h2),
                                            S[mt][2*kt+1][1] - bf2_hi(h2));
                    plo[mt][kt][3] = pk_bf2(S[mt][2*kt+1][2] - bf2_lo(h3),
                                            S[mt][2*kt+1][3] - bf2_hi(h3));
                }
            }

            // ---- O += P . V (3-term split: Phi*Vhi + Plo*Vhi + Phi*Vlo) ----
            #pragma unroll
            for (int pass = 0; pass < 3; pass++) {
                const uint32_t bcol = (pass == 2) ? 128u : 0u;   // V lo columns
                #pragma unroll
                for (int kt = 0; kt < 4; kt++) {
                    const uint32_t* A0 = (pass == 1) ? plo[0][kt] : phi[0][kt];
                    const uint32_t* A1 = (pass == 1) ? plo[1][kt] : phi[1][kt];
                    #pragma unroll
                    for (int np = 0; np < 4; np++) {
                        uint32_t b0, b1, b2, b3;
                        ldsm4(b0, b1, b2, b3,
                              sV + (uint32_t)(np * 16) * QSTR + bcol + kt * 32 + boff);
                        uint32_t bb0[2] = {b0, b1}, bb1[2] = {b2, b3};
                        mma16816(O[0][np * 2 + 0], A0, bb0);
                        mma16816(O[0][np * 2 + 1], A0, bb1);
                        mma16816(O[1][np * 2 + 0], A1, bb0);
                        mma16816(O[1][np * 2 + 1], A1, bb1);
                    }
                }
            }
        }
    }

    // ---- normalize + write ----
    #pragma unroll
    for (int mt = 0; mt < 2; mt++) {
        float inv0 = 1.f / lrow[mt][0], inv1 = 1.f / lrow[mt][1];
        int q0 = qwb + mt * 16 + (lid >> 2);
        float* o0 = g_O + ((size_t)b * T_ + q0) * C_ + h * 64 + (lid & 3) * 2;
        float* o1 = o0 + 8 * C_;
        #pragma unroll
        for (int nt = 0; nt < 8; nt++) {
            float2 v0, v1;
            v0.x = O[mt][nt][0] * inv0; v0.y = O[mt][nt][1] * inv0;
            v1.x = O[mt][nt][2] * inv1; v1.y = O[mt][nt][3] * inv1;
            *(float2*)(o0 + nt * 8) = v0;
            *(float2*)(o1 + nt * 8) = v1;
        }
    }
    #undef LOADKV
}

// ------------------------------- launcher -----------------------------------
extern "C" void kernel_launch(void* const* d_in, const int* in_sizes, int n_in,
                              void* d_out, int out_size) {
    const float* x    = (const float*)d_in[0];   // [4,2048,1024]
    const float* Wqkv = (const float*)d_in[1];   // [1024,3072]
    const float* bqkv = (const float*)d_in[2];   // [3072]
    const float* Wout = (const float*)d_in[3];   // [1024,1024]
    const float* bout = (const float*)d_in[4];   // [1024]
    float* out = (float*)d_out;                  // [4,2048,1024]

    cudaFuncSetAttribute(flash_mma_kernel,
                         cudaFuncAttributeMaxDynamicSharedMemorySize, FLASH_SMEM);
    cudaFuncSetAttribute(gemm_mma_kernel<0>,
                         cudaFuncAttributeMaxDynamicSharedMemorySize, GSMEM);
    cudaFuncSetAttribute(gemm_mma_kernel<1>,
                         cudaFuncAttributeMaxDynamicSharedMemorySize, GSMEM);

    unsigned short* gA  = nullptr; cudaGetSymbolAddress((void**)&gA,  g_A);
    unsigned short* gBq = nullptr; cudaGetSymbolAddress((void**)&gBq, g_Bq);
    unsigned short* gBo = nullptr; cudaGetSymbolAddress((void**)&gBo, g_Bo);
    float* gO = nullptr; cudaGetSymbolAddress((void**)&gO, g_O);

    // 1) split/transpose prep
    prep_split_kernel<<<8192, 256>>>(x, gA);
    prep_wsplit_kernel<3072><<<dim3(96, 32), dim3(32, 8)>>>(Wqkv, gBq);
    prep_wsplit_kernel<1024><<<dim3(32, 32), dim3(32, 8)>>>(Wout, gBo);

    // 2) QKV projection -> split bf16 Q/K/V^T (head-major)
    gemm_mma_kernel<0><<<dim3(24, 64), 128, GSMEM>>>(gA, gBq, bqkv, nullptr);

    // 3) causal flash attention (tensor cores) -> g_O [B,T,C]
    flash_mma_kernel<<<dim3(16, 16, 4), 128, FLASH_SMEM>>>();

    // 4) split g_O, output projection -> d_out
    prep_split_kernel<<<8192, 256>>>(gO, gA);
    gemm_mma_kernel<1><<<dim3(8, 64), 128, GSMEM>>>(gA, gBo, bout, out);
}

// round 12
// speedup vs baseline: 1.4897x; 1.4897x over previous
#include <cuda_runtime.h>
#include <cuda_fp16.h>
#include <cstdint>

#define B_   4
#define T_   2048
#define C_   1024
#define H_   16
#define D_   64
#define BT_  (B_*T_)
#define BH_  (B_*H_)
#define KL_  2048     // logical K for projections: [A_hi|A_lo] . [B_hi|B_hi]

// ------------------------- scratch (device globals) -------------------------
__device__ __align__(16) unsigned short g_A [BT_*KL_];       // x-split / O-split [hi|lo] fp16
__device__ __align__(16) unsigned short g_Bq[3*C_*C_];       // Wqkv^T hi fp16 [3072][1024]
__device__ __align__(16) unsigned short g_Bo[C_*C_];         // Wout^T hi fp16 [1024][1024]
__device__ __align__(16) unsigned short g_Qs[BH_*T_*128];    // [bh][t][Qhi64|Qlo64] fp16, pre-scaled
__device__ __align__(16) unsigned short g_Ks[BH_*T_*64];     // [bh][t][64] fp16 hi only
__device__ __align__(16) unsigned short g_Vt[BH_*64*T_];     // [bh][d][t] fp16 hi only

// ------------------------------ small helpers -------------------------------
__device__ __forceinline__ uint32_t s2u(const void* p) {
    uint32_t a;
    asm("{ .reg .u64 t; cvta.to.shared.u64 t, %1; cvt.u32.u64 %0, t; }" : "=r"(a) : "l"(p));
    return a;
}
__device__ __forceinline__ void cp16(uint32_t d, const void* s) {
    asm volatile("cp.async.cg.shared.global [%0], [%1], 16;" :: "r"(d), "l"(s));
}
__device__ __forceinline__ void ldsm4(uint32_t& r0, uint32_t& r1, uint32_t& r2, uint32_t& r3,
                                      uint32_t a) {
    asm volatile("ldmatrix.sync.aligned.m8n8.x4.shared.b16 {%0,%1,%2,%3}, [%4];"
                 : "=r"(r0), "=r"(r1), "=r"(r2), "=r"(r3) : "r"(a));
}
__device__ __forceinline__ void mma16816(float* c, const uint32_t* a, const uint32_t* b) {
    asm volatile("mma.sync.aligned.m16n8k16.row.col.f32.f16.f16.f32 "
                 "{%0,%1,%2,%3}, {%4,%5,%6,%7}, {%8,%9}, {%0,%1,%2,%3};"
                 : "+f"(c[0]), "+f"(c[1]), "+f"(c[2]), "+f"(c[3])
                 : "r"(a[0]), "r"(a[1]), "r"(a[2]), "r"(a[3]), "r"(b[0]), "r"(b[1]));
}
__device__ __forceinline__ uint32_t h2u(__half2 h) {
    return *reinterpret_cast<uint32_t*>(&h);
}
// split pair (x,y) into hi fp16x2 (x in low) + residual lo fp16x2
__device__ __forceinline__ void split2(float x, float y, uint32_t& hi, uint32_t& lo) {
    __half2 h = __floats2half2_rn(x, y);
    __half2 l = __floats2half2_rn(x - __low2float(h), y - __high2float(h));
    hi = h2u(h); lo = h2u(l);
}

// ------------------------------ prep kernels --------------------------------
// split fp32 [rows][1024] -> fp16 [rows][2048] = [hi | lo]
__global__ __launch_bounds__(256) void prep_split_kernel(
    const float* __restrict__ src, unsigned short* __restrict__ dst)
{
    int idx = blockIdx.x * 256 + threadIdx.x;
    int row = idx >> 8;
    int c4  = idx & 255;
    float4 v = *(const float4*)(src + (size_t)row * 1024 + c4 * 4);
    uint32_t h0, l0, h1, l1;
    split2(v.x, v.y, h0, l0);
    split2(v.z, v.w, h1, l1);
    unsigned short* rp = dst + (size_t)row * KL_ + c4 * 4;
    *(uint64_t*)(rp)        = (uint64_t)h0 | ((uint64_t)h1 << 32);
    *(uint64_t*)(rp + 1024) = (uint64_t)l0 | ((uint64_t)l1 << 32);
}

// transpose + truncate: W[1024][N] fp32 -> dst[N][1024] fp16 hi
template<int N>
__global__ __launch_bounds__(256) void prep_wsplit_kernel(
    const float* __restrict__ W, unsigned short* __restrict__ dst)
{
    __shared__ float tile[32][33];
    int n0 = blockIdx.x * 32, k0 = blockIdx.y * 32;
    int tx = threadIdx.x, ty = threadIdx.y;
    #pragma unroll
    for (int i = 0; i < 32; i += 8)
        tile[ty + i][tx] = W[(size_t)(k0 + ty + i) * N + n0 + tx];
    __syncthreads();
    #pragma unroll
    for (int i = 0; i < 32; i += 8) {
        int n = n0 + ty + i;
        int k = k0 + tx;
        __half hv = __float2half_rn(tile[tx][ty + i]);
        dst[(size_t)n * C_ + k] = *reinterpret_cast<unsigned short*>(&hv);
    }
}

// ---------------------- mma.sync fp16 GEMM (tensor core) ---------------------
// D[128,128] = A[128, 2048 = hi|lo] . B[128, 1024 hi]^T (B reused for both passes).
// 256 threads = 8 warps, warp tile 64x32, K-chunk 64, 2-stage, 1 sync/chunk.
#define TSTR2 144                        // bytes per 64-k row (128 B + 16 pad)
#define TILE2 (128 * TSTR2)              // 18432
#define STG2  (2 * TILE2)                // A+B per stage = 36864
#define GSMEM (2 * STG2)                 // 73728
#define NCHU  (KL_ / 64)                 // 32
#define ROWA  (KL_ * 2)                  // 4096 B
#define ROWB  (C_ * 2)                   // 2048 B

template<int MODE>
__global__ __launch_bounds__(256, 2) void gemm_mma_kernel(
    const unsigned short* __restrict__ A, const unsigned short* __restrict__ Bm,
    const float* __restrict__ bias, float* __restrict__ Cout)
{
    extern __shared__ __align__(128) char smem[];
    const uint32_t sb = s2u(smem);

    const int tid = threadIdx.x, wid = tid >> 5, lid = tid & 31;
    const int bm = blockIdx.y * 128, bn = blockIdx.x * 128;
    const int wm = (wid & 1) * 64, wn = (wid >> 1) * 32;

    const int g = lid >> 3, r = lid & 7;
    const uint32_t aoff = (uint32_t)(((g & 1) * 8 + r) * TSTR2 + (g >> 1) * 16);
    const uint32_t boff = (uint32_t)(((g >> 1) * 8 + r) * TSTR2 + (g & 1) * 16);

    const char* gA0 = (const char*)A  + (size_t)bm * ROWA;
    const char* gB0 = (const char*)Bm + (size_t)bn * ROWB;

    #define LOADCHUNK(kc, buf) do {                                            \
        int bc_ = (kc) & 15;              /* B hi reused in pass 1 */          \
        uint32_t b0 = sb + (buf) * STG2;                                       \
        _Pragma("unroll")                                                      \
        for (int i_ = 0; i_ < 4; i_++) {                                       \
            int idx_ = tid + i_ * 256;                                         \
            int row_ = idx_ >> 3, c_ = idx_ & 7;                               \
            cp16(b0 + (uint32_t)(row_ * TSTR2 + c_ * 16),                      \
                 gA0 + (size_t)row_ * ROWA + (kc) * 128 + c_ * 16);            \
            cp16(b0 + TILE2 + (uint32_t)(row_ * TSTR2 + c_ * 16),              \
                 gB0 + (size_t)row_ * ROWB + bc_ * 128 + c_ * 16);             \
        }                                                                      \
        asm volatile("cp.async.commit_group;" ::: "memory");                   \
    } while (0)

    float acc[4][4][4];
    #pragma unroll
    for (int mt = 0; mt < 4; mt++)
        #pragma unroll
        for (int nt = 0; nt < 4; nt++)
            #pragma unroll
            for (int i = 0; i < 4; i++) acc[mt][nt][i] = 0.f;

    LOADCHUNK(0, 0);

    for (int c = 0; c < NCHU; c++) {
        asm volatile("cp.async.wait_group 0;" ::: "memory");
        __syncthreads();
        if (c + 1 < NCHU) LOADCHUNK(c + 1, (c + 1) & 1);

        const uint32_t sAb = sb + (c & 1) * STG2;
        const uint32_t sBb = sAb + TILE2;
        #pragma unroll
        for (int ks = 0; ks < 4; ks++) {
            uint32_t a[4][4];
            #pragma unroll
            for (int mt = 0; mt < 4; mt++)
                ldsm4(a[mt][0], a[mt][1], a[mt][2], a[mt][3],
                      sAb + (uint32_t)((wm + mt * 16) * TSTR2 + ks * 32) + aoff);
            uint32_t b[4][2];
            #pragma unroll
            for (int nh = 0; nh < 2; nh++) {
                uint32_t r0, r1, r2, r3;
                ldsm4(r0, r1, r2, r3,
                      sBb + (uint32_t)((wn + nh * 16) * TSTR2 + ks * 32) + boff);
                b[nh*2+0][0] = r0; b[nh*2+0][1] = r1;
                b[nh*2+1][0] = r2; b[nh*2+1][1] = r3;
            }
            #pragma unroll
            for (int mt = 0; mt < 4; mt++)
                #pragma unroll
                for (int nt = 0; nt < 4; nt++)
                    mma16816(acc[mt][nt], a[mt], b[nt]);
        }
    }

    // ------------------------------- epilogue --------------------------------
    const int mrow = bm + wm + (lid >> 2);
    const int ncol = bn + wn + (lid & 3) * 2;
    #pragma unroll
    for (int mt = 0; mt < 4; mt++) {
        #pragma unroll
        for (int half = 0; half < 2; half++) {
            int m = mrow + mt * 16 + half * 8;
            #pragma unroll
            for (int nt = 0; nt < 4; nt++) {
                int col = ncol + nt * 8;
                float vx = acc[mt][nt][half * 2 + 0] + bias[col];
                float vy = acc[mt][nt][half * 2 + 1] + bias[col + 1];
                if (MODE == 0) {
                    const int which = bn >> 10;          // 0=Q 1=K 2=V
                    int ccv = col & 1023;
                    int hh = ccv >> 6, d = ccv & 63;
                    int bb = m >> 11, t = m & 2047;
                    int bh = bb * H_ + hh;
                    if (which == 0) {                    // Q: pre-scale, exact split
                        vx *= 0.125f; vy *= 0.125f;
                        uint32_t hi2, lo2;
                        split2(vx, vy, hi2, lo2);
                        size_t idx = ((size_t)bh * T_ + t) * 128 + d;
                        *(uint32_t*)&g_Qs[idx]      = hi2;
                        *(uint32_t*)&g_Qs[idx + 64] = lo2;
                    } else if (which == 1) {             // K: hi only
                        __half2 h = __floats2half2_rn(vx, vy);
                        *(uint32_t*)&g_Ks[((size_t)bh * T_ + t) * 64 + d] = h2u(h);
                    } else {                             // V: hi only, transposed
                        __half2 h = __floats2half2_rn(vx, vy);
                        uint32_t u = h2u(h);
                        size_t rb = (size_t)bh * 64;
                        g_Vt[(rb + d    ) * T_ + t] = (unsigned short)(u & 0xffff);
                        g_Vt[(rb + d + 1) * T_ + t] = (unsigned short)(u >> 16);
                    }
                } else {
                    float2 v; v.x = vx; v.y = vy;
                    *(float2*)&Cout[(size_t)m * 1024 + col] = v;
                }
            }
        }
    }
    #undef LOADCHUNK
}

// ------------------- flash attention (tensor core, fp16 2-pass) --------------
#define QSTR    272                      // Q smem row stride (256 B data + 16)
#define KSTR    144                      // K/V smem row stride (128 B data + 16)
#define FKT     (64 * KSTR)              // 9216 per K or V tile
#define FLASH_SMEM (128 * QSTR + 4 * FKT)   // 34816 + 36864 = 71680 -> 3 CTA/SM

__global__ __launch_bounds__(128) void flash_mma_kernel()
{
    extern __shared__ char fsm[];
    const uint32_t sQ  = s2u(fsm);
    const uint32_t sK0 = sQ + 128 * QSTR;
    const uint32_t sV0 = sK0 + 2 * FKT;

    const int tid = threadIdx.x, wid = tid >> 5, lid = tid & 31;
    const int qb = blockIdx.x * 128, h = blockIdx.y, b = blockIdx.z;
    const int bh = b * H_ + h;
    const int qwb = qb + wid * 32;

    const char* Qg = (const char*)(g_Qs + ((size_t)bh * T_ + qb) * 128);
    const char* Kg = (const char*)(g_Ks + ((size_t)bh * T_) * 64);
    const char* Vg = (const char*)(g_Vt + (size_t)bh * 64 * T_);

    // Q tile: 128 rows x 256 B
    #pragma unroll
    for (int i = 0; i < 16; i++) {
        int idx = tid + i * 128, row = idx >> 4, c16 = idx & 15;
        cp16(sQ + row * QSTR + c16 * 16, Qg + row * 256 + c16 * 16);
    }
    asm volatile("cp.async.commit_group;" ::: "memory");

    #define LOADKV(kb_, buf_) do {                                               \
        uint32_t sk = sK0 + (buf_) * FKT, sv = sV0 + (buf_) * FKT;               \
        _Pragma("unroll")                                                        \
        for (int i_ = 0; i_ < 4; i_++) {                                         \
            int idx = tid + i_ * 128, row = idx >> 3, c_ = idx & 7;              \
            cp16(sk + row * KSTR + c_ * 16,                                      \
                 Kg + (size_t)((kb_) + row) * 128 + c_ * 16);                    \
            cp16(sv + row * KSTR + c_ * 16,                                      \
                 Vg + (size_t)row * 4096 + (size_t)(kb_) * 2 + c_ * 16);         \
        }                                                                        \
        asm volatile("cp.async.commit_group;" ::: "memory");                     \
    } while (0)

    LOADKV(0, 0);

    const int g = lid >> 3, r = lid & 7;
    const uint32_t aoff  = (uint32_t)(((g & 1) * 8 + r) * QSTR + (g >> 1) * 16);
    const uint32_t boffK = (uint32_t)(((g >> 1) * 8 + r) * KSTR + (g & 1) * 16);
    const uint32_t qwoff = (uint32_t)(wid * 32) * QSTR;

    float O[2][8][4];
    #pragma unroll
    for (int mt = 0; mt < 2; mt++)
        #pragma unroll
        for (int nt = 0; nt < 8; nt++)
            #pragma unroll
            for (int i = 0; i < 4; i++) O[mt][nt][i] = 0.f;
    float mrow[2][2] = {{-1e30f, -1e30f}, {-1e30f, -1e30f}};
    float lrow[2][2] = {{0.f, 0.f}, {0.f, 0.f}};

    const int ntiles = (qb + 128) >> 6;

    for (int t = 0; t < ntiles; t++) {
        const int kb = t << 6;
        asm volatile("cp.async.wait_group 0;" ::: "memory");
        __syncthreads();
        if (t + 1 < ntiles) LOADKV((t + 1) << 6, (t + 1) & 1);

        if (kb <= qwb + 31) {
            const uint32_t sK = sK0 + (t & 1) * FKT;
            const uint32_t sV = sV0 + (t & 1) * FKT;

            // ---- S = Q . K^T : 2 passes (Qhi.Khi + Qlo.Khi); Q exact ----
            float S[2][8][4];
            #pragma unroll
            for (int mt = 0; mt < 2; mt++)
                #pragma unroll
                for (int nt = 0; nt < 8; nt++)
                    #pragma unroll
                    for (int i = 0; i < 4; i++) S[mt][nt][i] = 0.f;

            #pragma unroll
            for (int pass = 0; pass < 2; pass++) {
                const uint32_t aseg = pass ? 128u : 0u;   // Q lo segment
                #pragma unroll
                for (int kt = 0; kt < 4; kt++) {
                    uint32_t a0[4], a1[4];
                    ldsm4(a0[0], a0[1], a0[2], a0[3],
                          sQ + qwoff + aseg + kt * 32 + aoff);
                    ldsm4(a1[0], a1[1], a1[2], a1[3],
                          sQ + qwoff + 16 * QSTR + aseg + kt * 32 + aoff);
                    #pragma unroll
                    for (int np = 0; np < 4; np++) {
                        uint32_t b0, b1, b2, b3;
                        ldsm4(b0, b1, b2, b3,
                              sK + (uint32_t)(np * 16) * KSTR + kt * 32 + boffK);
                        uint32_t bb0[2] = {b0, b1}, bb1[2] = {b2, b3};
                        mma16816(S[0][np * 2 + 0], a0, bb0);
                        mma16816(S[0][np * 2 + 1], a0, bb1);
                        mma16816(S[1][np * 2 + 0], a1, bb0);
                        mma16816(S[1][np * 2 + 1], a1, bb1);
                    }
                }
            }

            // ---- causal mask ----
            if (kb + 63 > qwb) {
                #pragma unroll
                for (int mt = 0; mt < 2; mt++) {
                    int q0 = qwb + mt * 16 + (lid >> 2);
                    #pragma unroll
                    for (int nt = 0; nt < 8; nt++) {
                        int key = kb + nt * 8 + (lid & 3) * 2;
                        if (key     > q0)     S[mt][nt][0] = -1e30f;
                        if (key + 1 > q0)     S[mt][nt][1] = -1e30f;
                        if (key     > q0 + 8) S[mt][nt][2] = -1e30f;
                        if (key + 1 > q0 + 8) S[mt][nt][3] = -1e30f;
                    }
                }
            }

            // ---- online softmax + P exact fp16 split ----
            uint32_t phi[2][4][4], plo[2][4][4];
            #pragma unroll
            for (int mt = 0; mt < 2; mt++) {
                float mn0 = -1e30f, mn1 = -1e30f;
                #pragma unroll
                for (int nt = 0; nt < 8; nt++) {
                    mn0 = fmaxf(mn0, fmaxf(S[mt][nt][0], S[mt][nt][1]));
                    mn1 = fmaxf(mn1, fmaxf(S[mt][nt][2], S[mt][nt][3]));
                }
                mn0 = fmaxf(mn0, __shfl_xor_sync(0xffffffffu, mn0, 1));
                mn0 = fmaxf(mn0, __shfl_xor_sync(0xffffffffu, mn0, 2));
                mn1 = fmaxf(mn1, __shfl_xor_sync(0xffffffffu, mn1, 1));
                mn1 = fmaxf(mn1, __shfl_xor_sync(0xffffffffu, mn1, 2));
                float mx0 = fmaxf(mrow[mt][0], mn0), mx1 = fmaxf(mrow[mt][1], mn1);
                float al0 = __expf(mrow[mt][0] - mx0), al1 = __expf(mrow[mt][1] - mx1);
                mrow[mt][0] = mx0; mrow[mt][1] = mx1;
                float s0 = 0.f, s1 = 0.f;
                #pragma unroll
                for (int nt = 0; nt < 8; nt++) {
                    float p0 = __expf(S[mt][nt][0] - mx0);
                    float p1 = __expf(S[mt][nt][1] - mx0);
                    float p2 = __expf(S[mt][nt][2] - mx1);
                    float p3 = __expf(S[mt][nt][3] - mx1);
                    s0 += p0 + p1; s1 += p2 + p3;
                    S[mt][nt][0] = p0; S[mt][nt][1] = p1;
                    S[mt][nt][2] = p2; S[mt][nt][3] = p3;
                }
                s0 += __shfl_xor_sync(0xffffffffu, s0, 1);
                s0 += __shfl_xor_sync(0xffffffffu, s0, 2);
                s1 += __shfl_xor_sync(0xffffffffu, s1, 1);
                s1 += __shfl_xor_sync(0xffffffffu, s1, 2);
                lrow[mt][0] = lrow[mt][0] * al0 + s0;
                lrow[mt][1] = lrow[mt][1] * al1 + s1;
                #pragma unroll
                for (int nt = 0; nt < 8; nt++) {
                    O[mt][nt][0] *= al0; O[mt][nt][1] *= al0;
                    O[mt][nt][2] *= al1; O[mt][nt][3] *= al1;
                }
                // pack P fragments: C-frag(n-tiles 2kt,2kt+1) -> A-frag(k16 tile kt)
                #pragma unroll
                for (int kt = 0; kt < 4; kt++) {
                    split2(S[mt][2*kt  ][0], S[mt][2*kt  ][1], phi[mt][kt][0], plo[mt][kt][0]);
                    split2(S[mt][2*kt  ][2], S[mt][2*kt  ][3], phi[mt][kt][1], plo[mt][kt][1]);
                    split2(S[mt][2*kt+1][0], S[mt][2*kt+1][1], phi[mt][kt][2], plo[mt][kt][2]);
                    split2(S[mt][2*kt+1][2], S[mt][2*kt+1][3], phi[mt][kt][3], plo[mt][kt][3]);
                }
            }

            // ---- O += P . V : 2 passes (Phi.Vhi + Plo.Vhi); P exact ----
            #pragma unroll
            for (int pass = 0; pass < 2; pass++) {
                #pragma unroll
                for (int kt = 0; kt < 4; kt++) {
                    const uint32_t* A0 = pass ? plo[0][kt] : phi[0][kt];
                    const uint32_t* A1 = pass ? plo[1][kt] : phi[1][kt];
                    #pragma unroll
                    for (int np = 0; np < 4; np++) {
                        uint32_t b0, b1, b2, b3;
                        ldsm4(b0, b1, b2, b3,
                              sV + (uint32_t)(np * 16) * KSTR + kt * 32 + boffK);
                        uint32_t bb0[2] = {b0, b1}, bb1[2] = {b2, b3};
                        mma16816(O[0][np * 2 + 0], A0, bb0);
                        mma16816(O[0][np * 2 + 1], A0, bb1);
                        mma16816(O[1][np * 2 + 0], A1, bb0);
                        mma16816(O[1][np * 2 + 1], A1, bb1);
                    }
                }
            }
        }
    }

    // ---- normalize + write split fp16 O directly into g_A (skip prep pass) ----
    #pragma unroll
    for (int mt = 0; mt < 2; mt++) {
        float inv0 = 1.f / lrow[mt][0], inv1 = 1.f / lrow[mt][1];
        int q0 = qwb + mt * 16 + (lid >> 2);
        size_t row0 = (size_t)b * T_ + q0;
        int colb = h * 64 + (lid & 3) * 2;
        #pragma unroll
        for (int nt = 0; nt < 8; nt++) {
            int col = colb + nt * 8;
            uint32_t hi2, lo2;
            split2(O[mt][nt][0] * inv0, O[mt][nt][1] * inv0, hi2, lo2);
            *(uint32_t*)&g_A[row0 * KL_ + col]        = hi2;
            *(uint32_t*)&g_A[row0 * KL_ + 1024 + col] = lo2;
            split2(O[mt][nt][2] * inv1, O[mt][nt][3] * inv1, hi2, lo2);
            *(uint32_t*)&g_A[(row0 + 8) * KL_ + col]        = hi2;
            *(uint32_t*)&g_A[(row0 + 8) * KL_ + 1024 + col] = lo2;
        }
    }
    #undef LOADKV
}

// ------------------------------- launcher -----------------------------------
extern "C" void kernel_launch(void* const* d_in, const int* in_sizes, int n_in,
                              void* d_out, int out_size) {
    const float* x    = (const float*)d_in[0];   // [4,2048,1024]
    const float* Wqkv = (const float*)d_in[1];   // [1024,3072]
    const float* bqkv = (const float*)d_in[2];   // [3072]
    const float* Wout = (const float*)d_in[3];   // [1024,1024]
    const float* bout = (const float*)d_in[4];   // [1024]
    float* out = (float*)d_out;                  // [4,2048,1024]

    cudaFuncSetAttribute(flash_mma_kernel,
                         cudaFuncAttributeMaxDynamicSharedMemorySize, FLASH_SMEM);
    cudaFuncSetAttribute(gemm_mma_kernel<0>,
                         cudaFuncAttributeMaxDynamicSharedMemorySize, GSMEM);
    cudaFuncSetAttribute(gemm_mma_kernel<1>,
                         cudaFuncAttributeMaxDynamicSharedMemorySize, GSMEM);

    unsigned short* gA  = nullptr; cudaGetSymbolAddress((void**)&gA,  g_A);
    unsigned short* gBq = nullptr; cudaGetSymbolAddress((void**)&gBq, g_Bq);
    unsigned short* gBo = nullptr; cudaGetSymbolAddress((void**)&gBo, g_Bo);

    // 1) split/truncate prep
    prep_split_kernel<<<8192, 256>>>(x, gA);
    prep_wsplit_kernel<3072><<<dim3(96, 32), dim3(32, 8)>>>(Wqkv, gBq);
    prep_wsplit_kernel<1024><<<dim3(32, 32), dim3(32, 8)>>>(Wout, gBo);

    // 2) QKV projection -> fp16 Q(split)/K(hi)/V^T(hi), head-major
    gemm_mma_kernel<0><<<dim3(24, 64), 256, GSMEM>>>(gA, gBq, bqkv, nullptr);

    // 3) causal flash attention -> split-fp16 O written directly into g_A
    flash_mma_kernel<<<dim3(16, 16, 4), 128, FLASH_SMEM>>>();

    // 4) output projection -> d_out
    gemm_mma_kernel<1><<<dim3(8, 64), 256, GSMEM>>>(gA, gBo, bout, out);
}

// round 14
// speedup vs baseline: 2.5644x; 1.7214x over previous
#include <cuda_runtime.h>
#include <cuda_fp16.h>
#include <cstdint>

#define B_   4
#define T_   2048
#define C_   1024
#define H_   16
#define D_   64
#define BT_  (B_*T_)
#define BH_  (B_*H_)
#define KL_  1024     // K for projections, pure fp16 single-pass

// ------------------------- scratch (device globals) -------------------------
__device__ __align__(16) unsigned short g_A [BT_*KL_];       // x / O  fp16 [M][1024]
__device__ __align__(16) unsigned short g_Bq[3*C_*C_];       // Wqkv^T fp16 [3072][1024]
__device__ __align__(16) unsigned short g_Bo[C_*C_];         // Wout^T fp16 [1024][1024]
__device__ __align__(16) unsigned short g_Qs[BH_*T_*64];     // [bh][t][64] fp16, pre-scaled
__device__ __align__(16) unsigned short g_Ks[BH_*T_*64];     // [bh][t][64] fp16
__device__ __align__(16) unsigned short g_Vt[BH_*64*T_];     // [bh][d][t] fp16

// ------------------------------ small helpers -------------------------------
__device__ __forceinline__ uint32_t s2u(const void* p) {
    uint32_t a;
    asm("{ .reg .u64 t; cvta.to.shared.u64 t, %1; cvt.u32.u64 %0, t; }" : "=r"(a) : "l"(p));
    return a;
}
__device__ __forceinline__ void cp16(uint32_t d, const void* s) {
    asm volatile("cp.async.cg.shared.global [%0], [%1], 16;" :: "r"(d), "l"(s));
}
__device__ __forceinline__ void ldsm4(uint32_t& r0, uint32_t& r1, uint32_t& r2, uint32_t& r3,
                                      uint32_t a) {
    asm volatile("ldmatrix.sync.aligned.m8n8.x4.shared.b16 {%0,%1,%2,%3}, [%4];"
                 : "=r"(r0), "=r"(r1), "=r"(r2), "=r"(r3) : "r"(a));
}
__device__ __forceinline__ void mma16816(float* c, const uint32_t* a, const uint32_t* b) {
    asm volatile("mma.sync.aligned.m16n8k16.row.col.f32.f16.f16.f32 "
                 "{%0,%1,%2,%3}, {%4,%5,%6,%7}, {%8,%9}, {%0,%1,%2,%3};"
                 : "+f"(c[0]), "+f"(c[1]), "+f"(c[2]), "+f"(c[3])
                 : "r"(a[0]), "r"(a[1]), "r"(a[2]), "r"(a[3]), "r"(b[0]), "r"(b[1]));
}
__device__ __forceinline__ uint32_t h2u(__half2 h) {
    return *reinterpret_cast<uint32_t*>(&h);
}
__device__ __forceinline__ uint32_t pkh2(float x, float y) {
    __half2 h = __floats2half2_rn(x, y);
    return h2u(h);
}

// ------------------------------ prep kernels --------------------------------
// truncate fp32 [rows][1024] -> fp16 [rows][1024]
__global__ __launch_bounds__(256) void prep_split_kernel(
    const float* __restrict__ src, unsigned short* __restrict__ dst)
{
    int idx = blockIdx.x * 256 + threadIdx.x;
    float4 v = *(const float4*)(src + (size_t)idx * 4);
    uint64_t p = (uint64_t)pkh2(v.x, v.y) | ((uint64_t)pkh2(v.z, v.w) << 32);
    *(uint64_t*)(dst + (size_t)idx * 4) = p;
}

// transpose + truncate: W[1024][N] fp32 -> dst[N][1024] fp16
template<int N>
__global__ __launch_bounds__(256) void prep_wsplit_kernel(
    const float* __restrict__ W, unsigned short* __restrict__ dst)
{
    __shared__ float tile[32][33];
    int n0 = blockIdx.x * 32, k0 = blockIdx.y * 32;
    int tx = threadIdx.x, ty = threadIdx.y;
    #pragma unroll
    for (int i = 0; i < 32; i += 8)
        tile[ty + i][tx] = W[(size_t)(k0 + ty + i) * N + n0 + tx];
    __syncthreads();
    #pragma unroll
    for (int i = 0; i < 32; i += 8) {
        int n = n0 + ty + i;
        int k = k0 + tx;
        __half hv = __float2half_rn(tile[tx][ty + i]);
        dst[(size_t)n * C_ + k] = *reinterpret_cast<unsigned short*>(&hv);
    }
}

// ---------------------- mma.sync fp16 GEMM (tensor core) ---------------------
// D[128,128] = A[128,1024] . B[128,1024]^T, fp16, fp32 accum.
// 256 threads = 8 warps, warp tile 64x32, K-chunk 64, 2-stage, 1 sync/chunk.
#define TSTR2 144                        // bytes per 64-k row (128 B + 16 pad)
#define TILE2 (128 * TSTR2)              // 18432
#define STG2  (2 * TILE2)                // 36864
#define GSMEM (2 * STG2)                 // 73728
#define NCHU  (KL_ / 64)                 // 16
#define ROWA  (KL_ * 2)                  // 2048 B
#define ROWB  (C_ * 2)                   // 2048 B

template<int MODE>
__global__ __launch_bounds__(256, 2) void gemm_mma_kernel(
    const unsigned short* __restrict__ A, const unsigned short* __restrict__ Bm,
    const float* __restrict__ bias, float* __restrict__ Cout)
{
    extern __shared__ __align__(128) char smem[];
    const uint32_t sb = s2u(smem);

    const int tid = threadIdx.x, wid = tid >> 5, lid = tid & 31;
    const int bm = blockIdx.y * 128, bn = blockIdx.x * 128;
    const int wm = (wid & 1) * 64, wn = (wid >> 1) * 32;

    const int g = lid >> 3, r = lid & 7;
    const uint32_t aoff = (uint32_t)(((g & 1) * 8 + r) * TSTR2 + (g >> 1) * 16);
    const uint32_t boff = (uint32_t)(((g >> 1) * 8 + r) * TSTR2 + (g & 1) * 16);

    const char* gA0 = (const char*)A  + (size_t)bm * ROWA;
    const char* gB0 = (const char*)Bm + (size_t)bn * ROWB;

    #define LOADCHUNK(kc, buf) do {                                            \
        uint32_t b0 = sb + (buf) * STG2;                                       \
        _Pragma("unroll")                                                      \
        for (int i_ = 0; i_ < 4; i_++) {                                       \
            int idx_ = tid + i_ * 256;                                         \
            int row_ = idx_ >> 3, c_ = idx_ & 7;                               \
            cp16(b0 + (uint32_t)(row_ * TSTR2 + c_ * 16),                      \
                 gA0 + (size_t)row_ * ROWA + (kc) * 128 + c_ * 16);            \
            cp16(b0 + TILE2 + (uint32_t)(row_ * TSTR2 + c_ * 16),              \
                 gB0 + (size_t)row_ * ROWB + (kc) * 128 + c_ * 16);            \
        }                                                                      \
        asm volatile("cp.async.commit_group;" ::: "memory");                   \
    } while (0)

    float acc[4][4][4];
    #pragma unroll
    for (int mt = 0; mt < 4; mt++)
        #pragma unroll
        for (int nt = 0; nt < 4; nt++)
            #pragma unroll
            for (int i = 0; i < 4; i++) acc[mt][nt][i] = 0.f;

    LOADCHUNK(0, 0);

    for (int c = 0; c < NCHU; c++) {
        asm volatile("cp.async.wait_group 0;" ::: "memory");
        __syncthreads();
        if (c + 1 < NCHU) LOADCHUNK(c + 1, (c + 1) & 1);

        const uint32_t sAb = sb + (c & 1) * STG2;
        const uint32_t sBb = sAb + TILE2;
        #pragma unroll
        for (int ks = 0; ks < 4; ks++) {
            uint32_t a[4][4];
            #pragma unroll
            for (int mt = 0; mt < 4; mt++)
                ldsm4(a[mt][0], a[mt][1], a[mt][2], a[mt][3],
                      sAb + (uint32_t)((wm + mt * 16) * TSTR2 + ks * 32) + aoff);
            uint32_t b[4][2];
            #pragma unroll
            for (int nh = 0; nh < 2; nh++) {
                uint32_t r0, r1, r2, r3;
                ldsm4(r0, r1, r2, r3,
                      sBb + (uint32_t)((wn + nh * 16) * TSTR2 + ks * 32) + boff);
                b[nh*2+0][0] = r0; b[nh*2+0][1] = r1;
                b[nh*2+1][0] = r2; b[nh*2+1][1] = r3;
            }
            #pragma unroll
            for (int mt = 0; mt < 4; mt++)
                #pragma unroll
                for (int nt = 0; nt < 4; nt++)
                    mma16816(acc[mt][nt], a[mt], b[nt]);
        }
    }

    // ------------------------------- epilogue --------------------------------
    const int mrow = bm + wm + (lid >> 2);
    const int ncol = bn + wn + (lid & 3) * 2;
    #pragma unroll
    for (int mt = 0; mt < 4; mt++) {
        #pragma unroll
        for (int half = 0; half < 2; half++) {
            int m = mrow + mt * 16 + half * 8;
            #pragma unroll
            for (int nt = 0; nt < 4; nt++) {
                int col = ncol + nt * 8;
                float vx = acc[mt][nt][half * 2 + 0] + bias[col];
                float vy = acc[mt][nt][half * 2 + 1] + bias[col + 1];
                if (MODE == 0) {
                    const int which = bn >> 10;          // 0=Q 1=K 2=V
                    int ccv = col & 1023;
                    int hh = ccv >> 6, d = ccv & 63;
                    int bb = m >> 11, t = m & 2047;
                    int bh = bb * H_ + hh;
                    if (which == 0) {                    // Q: pre-scale 1/8
                        *(uint32_t*)&g_Qs[((size_t)bh * T_ + t) * 64 + d] =
                            pkh2(vx * 0.125f, vy * 0.125f);
                    } else if (which == 1) {             // K
                        *(uint32_t*)&g_Ks[((size_t)bh * T_ + t) * 64 + d] =
                            pkh2(vx, vy);
                    } else {                             // V transposed
                        uint32_t u = pkh2(vx, vy);
                        size_t rb = (size_t)bh * 64;
                        g_Vt[(rb + d    ) * T_ + t] = (unsigned short)(u & 0xffff);
                        g_Vt[(rb + d + 1) * T_ + t] = (unsigned short)(u >> 16);
                    }
                } else {
                    float2 v; v.x = vx; v.y = vy;
                    *(float2*)&Cout[(size_t)m * 1024 + col] = v;
                }
            }
        }
    }
    #undef LOADCHUNK
}

// ------------------- flash attention (tensor core, fp16 1-pass) --------------
#define KSTR    144                      // smem row stride (128 B data + 16)
#define FKT     (64 * KSTR)              // 9216 per K or V tile
#define FLASH_SMEM (128 * KSTR + 4 * FKT)   // 18432 + 36864 = 55296

__global__ __launch_bounds__(128) void flash_mma_kernel()
{
    extern __shared__ char fsm[];
    const uint32_t sQ  = s2u(fsm);
    const uint32_t sK0 = sQ + 128 * KSTR;
    const uint32_t sV0 = sK0 + 2 * FKT;

    const int tid = threadIdx.x, wid = tid >> 5, lid = tid & 31;
    const int qb = blockIdx.x * 128, h = blockIdx.y, b = blockIdx.z;
    const int bh = b * H_ + h;
    const int qwb = qb + wid * 32;

    const char* Qg = (const char*)(g_Qs + ((size_t)bh * T_ + qb) * 64);
    const char* Kg = (const char*)(g_Ks + ((size_t)bh * T_) * 64);
    const char* Vg = (const char*)(g_Vt + (size_t)bh * 64 * T_);

    // Q tile: 128 rows x 128 B
    #pragma unroll
    for (int i = 0; i < 8; i++) {
        int idx = tid + i * 128, row = idx >> 3, c_ = idx & 7;
        cp16(sQ + row * KSTR + c_ * 16, Qg + row * 128 + c_ * 16);
    }
    asm volatile("cp.async.commit_group;" ::: "memory");

    #define LOADKV(kb_, buf_) do {                                               \
        uint32_t sk = sK0 + (buf_) * FKT, sv = sV0 + (buf_) * FKT;               \
        _Pragma("unroll")                                                        \
        for (int i_ = 0; i_ < 4; i_++) {                                         \
            int idx = tid + i_ * 128, row = idx >> 3, c_ = idx & 7;              \
            cp16(sk + row * KSTR + c_ * 16,                                      \
                 Kg + (size_t)((kb_) + row) * 128 + c_ * 16);                    \
            cp16(sv + row * KSTR + c_ * 16,                                      \
                 Vg + (size_t)row * 4096 + (size_t)(kb_) * 2 + c_ * 16);         \
        }                                                                        \
        asm volatile("cp.async.commit_group;" ::: "memory");                     \
    } while (0)

    LOADKV(0, 0);

    const int g = lid >> 3, r = lid & 7;
    const uint32_t aoff  = (uint32_t)(((g & 1) * 8 + r) * KSTR + (g >> 1) * 16);
    const uint32_t boffK = (uint32_t)(((g >> 1) * 8 + r) * KSTR + (g & 1) * 16);
    const uint32_t qwoff = (uint32_t)(wid * 32) * KSTR;

    float O[2][8][4];
    #pragma unroll
    for (int mt = 0; mt < 2; mt++)
        #pragma unroll
        for (int nt = 0; nt < 8; nt++)
            #pragma unroll
            for (int i = 0; i < 4; i++) O[mt][nt][i] = 0.f;
    float mrow[2][2] = {{-1e30f, -1e30f}, {-1e30f, -1e30f}};
    float lrow[2][2] = {{0.f, 0.f}, {0.f, 0.f}};

    const int ntiles = (qb + 128) >> 6;

    for (int t = 0; t < ntiles; t++) {
        const int kb = t << 6;
        asm volatile("cp.async.wait_group 0;" ::: "memory");
        __syncthreads();
        if (t + 1 < ntiles) LOADKV((t + 1) << 6, (t + 1) & 1);

        if (kb <= qwb + 31) {
            const uint32_t sK = sK0 + (t & 1) * FKT;
            const uint32_t sV = sV0 + (t & 1) * FKT;

            // ---- S = Q . K^T (single fp16 pass) ----
            float S[2][8][4];
            #pragma unroll
            for (int mt = 0; mt < 2; mt++)
                #pragma unroll
                for (int nt = 0; nt < 8; nt++)
                    #pragma unroll
                    for (int i = 0; i < 4; i++) S[mt][nt][i] = 0.f;

            #pragma unroll
            for (int kt = 0; kt < 4; kt++) {
                uint32_t a0[4], a1[4];
                ldsm4(a0[0], a0[1], a0[2], a0[3],
                      sQ + qwoff + kt * 32 + aoff);
                ldsm4(a1[0], a1[1], a1[2], a1[3],
                      sQ + qwoff + 16 * KSTR + kt * 32 + aoff);
                #pragma unroll
                for (int np = 0; np < 4; np++) {
                    uint32_t b0, b1, b2, b3;
                    ldsm4(b0, b1, b2, b3,
                          sK + (uint32_t)(np * 16) * KSTR + kt * 32 + boffK);
                    uint32_t bb0[2] = {b0, b1}, bb1[2] = {b2, b3};
                    mma16816(S[0][np * 2 + 0], a0, bb0);
                    mma16816(S[0][np * 2 + 1], a0, bb1);
                    mma16816(S[1][np * 2 + 0], a1, bb0);
                    mma16816(S[1][np * 2 + 1], a1, bb1);
                }
            }

            // ---- causal mask ----
            if (kb + 63 > qwb) {
                #pragma unroll
                for (int mt = 0; mt < 2; mt++) {
                    int q0 = qwb + mt * 16 + (lid >> 2);
                    #pragma unroll
                    for (int nt = 0; nt < 8; nt++) {
                        int key = kb + nt * 8 + (lid & 3) * 2;
                        if (key     > q0)     S[mt][nt][0] = -1e30f;
                        if (key + 1 > q0)     S[mt][nt][1] = -1e30f;
                        if (key     > q0 + 8) S[mt][nt][2] = -1e30f;
                        if (key + 1 > q0 + 8) S[mt][nt][3] = -1e30f;
                    }
                }
            }

            // ---- online softmax ----
            uint32_t phi[2][4][4];
            #pragma unroll
            for (int mt = 0; mt < 2; mt++) {
                float mn0 = -1e30f, mn1 = -1e30f;
                #pragma unroll
                for (int nt = 0; nt < 8; nt++) {
                    mn0 = fmaxf(mn0, fmaxf(S[mt][nt][0], S[mt][nt][1]));
                    mn1 = fmaxf(mn1, fmaxf(S[mt][nt][2], S[mt][nt][3]));
                }
                mn0 = fmaxf(mn0, __shfl_xor_sync(0xffffffffu, mn0, 1));
                mn0 = fmaxf(mn0, __shfl_xor_sync(0xffffffffu, mn0, 2));
                mn1 = fmaxf(mn1, __shfl_xor_sync(0xffffffffu, mn1, 1));
                mn1 = fmaxf(mn1, __shfl_xor_sync(0xffffffffu, mn1, 2));
                float mx0 = fmaxf(mrow[mt][0], mn0), mx1 = fmaxf(mrow[mt][1], mn1);
                float al0 = __expf(mrow[mt][0] - mx0), al1 = __expf(mrow[mt][1] - mx1);
                mrow[mt][0] = mx0; mrow[mt][1] = mx1;
                float s0 = 0.f, s1 = 0.f;
                #pragma unroll
                for (int nt = 0; nt < 8; nt++) {
                    float p0 = __expf(S[mt][nt][0] - mx0);
                    float p1 = __expf(S[mt][nt][1] - mx0);
                    float p2 = __expf(S[mt][nt][2] - mx1);
                    float p3 = __expf(S[mt][nt][3] - mx1);
                    s0 += p0 + p1; s1 += p2 + p3;
                    S[mt][nt][0] = p0; S[mt][nt][1] = p1;
                    S[mt][nt][2] = p2; S[mt][nt][3] = p3;
                }
                s0 += __shfl_xor_sync(0xffffffffu, s0, 1);
                s0 += __shfl_xor_sync(0xffffffffu, s0, 2);
                s1 += __shfl_xor_sync(0xffffffffu, s1, 1);
                s1 += __shfl_xor_sync(0xffffffffu, s1, 2);
                lrow[mt][0] = lrow[mt][0] * al0 + s0;
                lrow[mt][1] = lrow[mt][1] * al1 + s1;
                #pragma unroll
                for (int nt = 0; nt < 8; nt++) {
                    O[mt][nt][0] *= al0; O[mt][nt][1] *= al0;
                    O[mt][nt][2] *= al1; O[mt][nt][3] *= al1;
                }
                // pack P: C-frag(n-tiles 2kt,2kt+1) -> A-frag(k16 tile kt)
                #pragma unroll
                for (int kt = 0; kt < 4; kt++) {
                    phi[mt][kt][0] = pkh2(S[mt][2*kt  ][0], S[mt][2*kt  ][1]);
                    phi[mt][kt][1] = pkh2(S[mt][2*kt  ][2], S[mt][2*kt  ][3]);
                    phi[mt][kt][2] = pkh2(S[mt][2*kt+1][0], S[mt][2*kt+1][1]);
                    phi[mt][kt][3] = pkh2(S[mt][2*kt+1][2], S[mt][2*kt+1][3]);
                }
            }

            // ---- O += P . V (single fp16 pass) ----
            #pragma unroll
            for (int kt = 0; kt < 4; kt++) {
                #pragma unroll
                for (int np = 0; np < 4; np++) {
                    uint32_t b0, b1, b2, b3;
                    ldsm4(b0, b1, b2, b3,
                          sV + (uint32_t)(np * 16) * KSTR + kt * 32 + boffK);
                    uint32_t bb0[2] = {b0, b1}, bb1[2] = {b2, b3};
                    mma16816(O[0][np * 2 + 0], phi[0][kt], bb0);
                    mma16816(O[0][np * 2 + 1], phi[0][kt], bb1);
                    mma16816(O[1][np * 2 + 0], phi[1][kt], bb0);
                    mma16816(O[1][np * 2 + 1], phi[1][kt], bb1);
                }
            }
        }
    }

    // ---- normalize + write fp16 O directly into g_A ----
    #pragma unroll
    for (int mt = 0; mt < 2; mt++) {
        float inv0 = 1.f / lrow[mt][0], inv1 = 1.f / lrow[mt][1];
        int q0 = qwb + mt * 16 + (lid >> 2);
        size_t row0 = (size_t)b * T_ + q0;
        int colb = h * 64 + (lid & 3) * 2;
        #pragma unroll
        for (int nt = 0; nt < 8; nt++) {
            int col = colb + nt * 8;
            *(uint32_t*)&g_A[row0 * KL_ + col] =
                pkh2(O[mt][nt][0] * inv0, O[mt][nt][1] * inv0);
            *(uint32_t*)&g_A[(row0 + 8) * KL_ + col] =
                pkh2(O[mt][nt][2] * inv1, O[mt][nt][3] * inv1);
        }
    }
    #undef LOADKV
}

// ------------------------------- launcher -----------------------------------
extern "C" void kernel_launch(void* const* d_in, const int* in_sizes, int n_in,
                              void* d_out, int out_size) {
    const float* x    = (const float*)d_in[0];   // [4,2048,1024]
    const float* Wqkv = (const float*)d_in[1];   // [1024,3072]
    const float* bqkv = (const float*)d_in[2];   // [3072]
    const float* Wout = (const float*)d_in[3];   // [1024,1024]
    const float* bout = (const float*)d_in[4];   // [1024]
    float* out = (float*)d_out;                  // [4,2048,1024]

    cudaFuncSetAttribute(flash_mma_kernel,
                         cudaFuncAttributeMaxDynamicSharedMemorySize, FLASH_SMEM);
    cudaFuncSetAttribute(gemm_mma_kernel<0>,
                         cudaFuncAttributeMaxDynamicSharedMemorySize, GSMEM);
    cudaFuncSetAttribute(gemm_mma_kernel<1>,
                         cudaFuncAttributeMaxDynamicSharedMemorySize, GSMEM);

    unsigned short* gA  = nullptr; cudaGetSymbolAddress((void**)&gA,  g_A);
    unsigned short* gBq = nullptr; cudaGetSymbolAddress((void**)&gBq, g_Bq);
    unsigned short* gBo = nullptr; cudaGetSymbolAddress((void**)&gBo, g_Bo);

    // 1) truncate/transpose prep
    prep_split_kernel<<<8192, 256>>>(x, gA);
    prep_wsplit_kernel<3072><<<dim3(96, 32), dim3(32, 8)>>>(Wqkv, gBq);
    prep_wsplit_kernel<1024><<<dim3(32, 32), dim3(32, 8)>>>(Wout, gBo);

    // 2) QKV projection -> fp16 Q/K/V^T, head-major
    gemm_mma_kernel<0><<<dim3(24, 64), 256, GSMEM>>>(gA, gBq, bqkv, nullptr);

    // 3) causal flash attention -> fp16 O written directly into g_A
    flash_mma_kernel<<<dim3(16, 16, 4), 128, FLASH_SMEM>>>();

    // 4) output projection -> d_out
    gemm_mma_kernel<1><<<dim3(8, 64), 256, GSMEM>>>(gA, gBo, bout, out);
}